// round 1
// baseline (speedup 1.0000x reference)
#include <cuda_runtime.h>

#define T_DIM 2048
#define B_DIM 2
#define E_DIM 1024
#define H_DIM 16
#define D_DIM 64
#define M_DIM (T_DIM * B_DIM)   // 4096 rows (t*B + b)

// Scratch (allocation-free rule: __device__ globals)
__device__ float g_q[(size_t)B_DIM * H_DIM * T_DIM * D_DIM];   // [B,H,T,D]
__device__ float g_k[(size_t)B_DIM * H_DIM * T_DIM * D_DIM];
__device__ float g_v[(size_t)B_DIM * H_DIM * T_DIM * D_DIM];
__device__ float g_ctx[(size_t)M_DIM * E_DIM];                 // [T,B,E]

// ----------------------------------------------------------------------------
// GEMM: Y[m,n] = (sum_k X[m,k] * W[n,k] + bias[n]) * scale
//   mode 0: scatter into [B,H,T,D] layout (for Q/K/V)
//   mode 1: plain [M, E] row-major (ctx @ Wo^T, final output)
// 64x64 block tile, BK=16, 256 threads, 4x4 micro-tile.
// ----------------------------------------------------------------------------
__global__ __launch_bounds__(256) void gemm_proj(
    const float* __restrict__ X, const float* __restrict__ W,
    const float* __restrict__ bias, float scale,
    float* __restrict__ Y, int mode)
{
    __shared__ float As[16 * 68];   // transposed [k][m], stride 68
    __shared__ float Bs[16 * 68];   // transposed [k][n]

    const int tid = threadIdx.x;
    const int tx = tid & 15;
    const int ty = tid >> 4;
    const int m0 = blockIdx.y << 6;
    const int n0 = blockIdx.x << 6;

    const int lrow = tid >> 2;        // 0..63
    const int lc   = (tid & 3) << 2;  // 0,4,8,12

    const float* Ap = X + (size_t)(m0 + lrow) * E_DIM + lc;
    const float* Bp = W + (size_t)(n0 + lrow) * E_DIM + lc;

    float acc[4][4];
#pragma unroll
    for (int i = 0; i < 4; i++)
#pragma unroll
        for (int j = 0; j < 4; j++) acc[i][j] = 0.f;

    for (int k0 = 0; k0 < E_DIM; k0 += 16) {
        float4 a = *(const float4*)(Ap + k0);
        float4 b = *(const float4*)(Bp + k0);
        __syncthreads();  // previous compute done before overwrite
        As[(lc + 0) * 68 + lrow] = a.x;
        As[(lc + 1) * 68 + lrow] = a.y;
        As[(lc + 2) * 68 + lrow] = a.z;
        As[(lc + 3) * 68 + lrow] = a.w;
        Bs[(lc + 0) * 68 + lrow] = b.x;
        Bs[(lc + 1) * 68 + lrow] = b.y;
        Bs[(lc + 2) * 68 + lrow] = b.z;
        Bs[(lc + 3) * 68 + lrow] = b.w;
        __syncthreads();
#pragma unroll
        for (int kk = 0; kk < 16; kk++) {
            float4 av = *(const float4*)(As + kk * 68 + (ty << 2));
            float4 bv = *(const float4*)(Bs + kk * 68 + (tx << 2));
            float ar[4] = {av.x, av.y, av.z, av.w};
            float br[4] = {bv.x, bv.y, bv.z, bv.w};
#pragma unroll
            for (int i = 0; i < 4; i++)
#pragma unroll
                for (int j = 0; j < 4; j++)
                    acc[i][j] = fmaf(ar[i], br[j], acc[i][j]);
        }
    }

#pragma unroll
    for (int i = 0; i < 4; i++) {
        const int m = m0 + (ty << 2) + i;
#pragma unroll
        for (int j = 0; j < 4; j++) {
            const int n = n0 + (tx << 2) + j;
            const float val = (acc[i][j] + bias[n]) * scale;
            if (mode == 0) {
                const int t = m >> 1, bb = m & 1;     // m = t*B + b, B=2
                const int h = n >> 6, d = n & 63;     // n = h*D + d, D=64
                Y[(((size_t)bb * H_DIM + h) * T_DIM + t) * D_DIM + d] = val;
            } else {
                Y[(size_t)m * E_DIM + n] = val;
            }
        }
    }
}

// ----------------------------------------------------------------------------
// Flash attention, fp32. One block = one (b,h) head x 64-query tile.
// 256 threads; thread (ty,tx) owns a 4x4 micro-tile of S and of O.
// Online softmax: per-row stats replicated across the 16 lanes of a row group.
// ----------------------------------------------------------------------------
__global__ __launch_bounds__(256) void flash_attn(
    const float* __restrict__ Q, const float* __restrict__ K,
    const float* __restrict__ V, float* __restrict__ ctx)
{
    extern __shared__ float sm[];
    float* Qs = sm;                   // 64 x 65
    float* Ks = sm + 64 * 65;         // 64 x 65
    float* Ps = sm + 2 * 64 * 65;     // 64 x 65
    float* Vs = sm + 3 * 64 * 65;     // 64 x 64 (float4 friendly)

    const int tid = threadIdx.x;
    const int tx = tid & 15;
    const int ty = tid >> 4;
    const int bh = blockIdx.y;                  // b*H + h
    const int q0 = blockIdx.x << 6;
    const size_t base = (size_t)bh * T_DIM * D_DIM;

    // Load Q tile [64 x 64] -> Qs (stride 65)
#pragma unroll
    for (int i = 0; i < 4; i++) {
        const int lin = tid + i * 256;
        const int r = lin >> 4;
        const int c = (lin & 15) << 2;
        float4 qv = *(const float4*)(Q + base + (size_t)(q0 + r) * D_DIM + c);
        Qs[r * 65 + c + 0] = qv.x;
        Qs[r * 65 + c + 1] = qv.y;
        Qs[r * 65 + c + 2] = qv.z;
        Qs[r * 65 + c + 3] = qv.w;
    }

    float m_i[4], l_i[4], acc[4][4];
#pragma unroll
    for (int i = 0; i < 4; i++) {
        m_i[i] = -3.0e38f;
        l_i[i] = 0.f;
#pragma unroll
        for (int j = 0; j < 4; j++) acc[i][j] = 0.f;
    }

    for (int kt = 0; kt < T_DIM / 64; kt++) {
        const int j0 = kt << 6;
        __syncthreads();  // prior PV reads of Vs/Ps done (also fences Q load 1st iter)

        // Load K -> Ks (stride 65), V -> Vs (stride 64)
#pragma unroll
        for (int i = 0; i < 4; i++) {
            const int lin = tid + i * 256;
            const int r = lin >> 4;
            const int c = (lin & 15) << 2;
            float4 kv = *(const float4*)(K + base + (size_t)(j0 + r) * D_DIM + c);
            Ks[r * 65 + c + 0] = kv.x;
            Ks[r * 65 + c + 1] = kv.y;
            Ks[r * 65 + c + 2] = kv.z;
            Ks[r * 65 + c + 3] = kv.w;
            float4 vv = *(const float4*)(V + base + (size_t)(j0 + r) * D_DIM + c);
            *(float4*)(Vs + r * 64 + c) = vv;
        }
        __syncthreads();

        // S = Q K^T  (Q already pre-scaled by D^-0.5 in projection)
        float s[4][4];
#pragma unroll
        for (int i = 0; i < 4; i++)
#pragma unroll
            for (int j = 0; j < 4; j++) s[i][j] = 0.f;

#pragma unroll 8
        for (int d = 0; d < 64; d++) {
            float qr[4], kr[4];
#pragma unroll
            for (int i = 0; i < 4; i++) qr[i] = Qs[((ty << 2) + i) * 65 + d];
#pragma unroll
            for (int j = 0; j < 4; j++) kr[j] = Ks[((tx << 2) + j) * 65 + d];
#pragma unroll
            for (int i = 0; i < 4; i++)
#pragma unroll
                for (int j = 0; j < 4; j++)
                    s[i][j] = fmaf(qr[i], kr[j], s[i][j]);
        }

        // Online softmax per row (rows ty*4+i; 16 lanes of same ty cooperate)
#pragma unroll
        for (int i = 0; i < 4; i++) {
            float mx = fmaxf(fmaxf(s[i][0], s[i][1]), fmaxf(s[i][2], s[i][3]));
#pragma unroll
            for (int off = 8; off > 0; off >>= 1)
                mx = fmaxf(mx, __shfl_xor_sync(0xffffffffu, mx, off, 16));
            const float nm = fmaxf(m_i[i], mx);
            const float al = __expf(m_i[i] - nm);
            float p[4], ts = 0.f;
#pragma unroll
            for (int j = 0; j < 4; j++) {
                p[j] = __expf(s[i][j] - nm);
                ts += p[j];
            }
#pragma unroll
            for (int off = 8; off > 0; off >>= 1)
                ts += __shfl_xor_sync(0xffffffffu, ts, off, 16);
            l_i[i] = l_i[i] * al + ts;
            m_i[i] = nm;
#pragma unroll
            for (int c = 0; c < 4; c++) acc[i][c] *= al;
#pragma unroll
            for (int j = 0; j < 4; j++)
                Ps[((ty << 2) + i) * 65 + (tx << 2) + j] = p[j];
        }
        __syncthreads();

        // O += P @ V
#pragma unroll 4
        for (int j = 0; j < 64; j++) {
            float4 vv = *(const float4*)(Vs + j * 64 + (tx << 2));
#pragma unroll
            for (int i = 0; i < 4; i++) {
                const float pij = Ps[((ty << 2) + i) * 65 + j];
                acc[i][0] = fmaf(pij, vv.x, acc[i][0]);
                acc[i][1] = fmaf(pij, vv.y, acc[i][1]);
                acc[i][2] = fmaf(pij, vv.z, acc[i][2]);
                acc[i][3] = fmaf(pij, vv.w, acc[i][3]);
            }
        }
    }

    // Epilogue: O /= l, write ctx in [T,B,E] layout
    const int b = bh >> 4;
    const int h = bh & 15;
#pragma unroll
    for (int i = 0; i < 4; i++) {
        const float inv = 1.f / l_i[i];
        const int t = q0 + (ty << 2) + i;
        float4 o;
        o.x = acc[i][0] * inv;
        o.y = acc[i][1] * inv;
        o.z = acc[i][2] * inv;
        o.w = acc[i][3] * inv;
        *(float4*)(ctx + (size_t)(t * B_DIM + b) * E_DIM + h * D_DIM + (tx << 2)) = o;
    }
}

// ----------------------------------------------------------------------------
extern "C" void kernel_launch(void* const* d_in, const int* in_sizes, int n_in,
                              void* d_out, int out_size)
{
    const float* x  = (const float*)d_in[0];
    const float* wq = (const float*)d_in[1];
    const float* bq = (const float*)d_in[2];
    const float* wk = (const float*)d_in[3];
    const float* bk = (const float*)d_in[4];
    const float* wv = (const float*)d_in[5];
    const float* bv = (const float*)d_in[6];
    const float* wo = (const float*)d_in[7];
    const float* bo = (const float*)d_in[8];
    float* out = (float*)d_out;

    float *q, *k, *v, *ctx;
    cudaGetSymbolAddress((void**)&q, g_q);
    cudaGetSymbolAddress((void**)&k, g_k);
    cudaGetSymbolAddress((void**)&v, g_v);
    cudaGetSymbolAddress((void**)&ctx, g_ctx);

    const dim3 gg(E_DIM / 64, M_DIM / 64);  // (16, 64)
    const float scaling = 0.125f;           // D^-0.5, D=64

    gemm_proj<<<gg, 256>>>(x, wq, bq, scaling, q, 0);
    gemm_proj<<<gg, 256>>>(x, wk, bk, 1.0f,    k, 0);
    gemm_proj<<<gg, 256>>>(x, wv, bv, 1.0f,    v, 0);

    const int smem = (3 * 64 * 65 + 64 * 64) * (int)sizeof(float);  // 66304 B
    cudaFuncSetAttribute(flash_attn, cudaFuncAttributeMaxDynamicSharedMemorySize, smem);
    flash_attn<<<dim3(T_DIM / 64, B_DIM * H_DIM), 256, smem>>>(q, k, v, ctx);

    gemm_proj<<<gg, 256>>>(ctx, wo, bo, 1.0f, out, 1);
}

// round 2
// speedup vs baseline: 2.3152x; 2.3152x over previous
#include <cuda_runtime.h>

#define T_DIM 2048
#define B_DIM 2
#define E_DIM 1024
#define H_DIM 16
#define D_DIM 64
#define M_DIM (T_DIM * B_DIM)   // 4096

// Scratch (allocation-free rule: __device__ globals)
__device__ float g_q[(size_t)B_DIM * H_DIM * T_DIM * D_DIM];   // [B,H,T,D]
__device__ float g_k[(size_t)B_DIM * H_DIM * T_DIM * D_DIM];
__device__ float g_v[(size_t)B_DIM * H_DIM * T_DIM * D_DIM];
__device__ float g_ctx[(size_t)M_DIM * E_DIM];                 // [T,B,E]

// ---------------------------------------------------------------------------
// helpers
// ---------------------------------------------------------------------------
__device__ __forceinline__ unsigned cvt_tf32(float x) {
    unsigned r;
    asm("cvt.rna.tf32.f32 %0, %1;" : "=r"(r) : "f"(x));
    return r;
}

__device__ __forceinline__ void mma_m16n8k8(float* c, const unsigned* a,
                                            unsigned b0, unsigned b1) {
    asm volatile(
        "mma.sync.aligned.m16n8k8.row.col.f32.tf32.tf32.f32 "
        "{%0,%1,%2,%3}, {%4,%5,%6,%7}, {%8,%9}, {%0,%1,%2,%3};\n"
        : "+f"(c[0]), "+f"(c[1]), "+f"(c[2]), "+f"(c[3])
        : "r"(a[0]), "r"(a[1]), "r"(a[2]), "r"(a[3]), "r"(b0), "r"(b1));
}

// exp(x) for x <= 0 on the FMA pipe (no MUFU). Clamp keeps result normal.
__device__ __forceinline__ float fexp(float x) {
    x = fmaxf(x, -80.0f);
    float t = x * 1.4426950408889634f;
    float fn = t + 12582912.0f;            // round-to-nearest int (magic)
    float n = fn - 12582912.0f;
    float r = t - n;                        // r in [-0.5, 0.5]
    float p = 1.3333558146e-3f;
    p = fmaf(p, r, 9.6181291890e-3f);
    p = fmaf(p, r, 5.5504108664e-2f);
    p = fmaf(p, r, 2.4022650696e-1f);
    p = fmaf(p, r, 6.9314718056e-1f);
    p = fmaf(p, r, 1.0f);
    int e = __float_as_int(fn) - 0x4B400000;   // == (int)n
    return __int_as_float(__float_as_int(p) + (e << 23));
}

// ---------------------------------------------------------------------------
// GEMM (tf32 tensor cores): Y[m,n] = (sum_k X[m,k]*W[n,k] + bias[n]) * scale
// Block 128x128, BK=16, 256 threads = 8 warps (2x4), warp tile 64x32.
// mode 0: scatter into [B,H,T,D]; mode 1: row-major [M, E].
// ---------------------------------------------------------------------------
__device__ __forceinline__ void store_out(float* __restrict__ Y, int m, int n,
                                          float v0, float v1, int mode) {
    if (mode == 0) {
        const int t = m >> 1, b = m & 1;      // m = t*B + b (B=2)
        const int h = n >> 6, d = n & 63;     // n = h*64 + d
        *(float2*)(Y + (((size_t)b * H_DIM + h) * T_DIM + t) * D_DIM + d) =
            make_float2(v0, v1);
    } else {
        *(float2*)(Y + (size_t)m * E_DIM + n) = make_float2(v0, v1);
    }
}

__global__ __launch_bounds__(256) void gemm_tc(
    const float* __restrict__ X, const float* __restrict__ W,
    const float* __restrict__ bias, float scale,
    float* __restrict__ Y, int mode)
{
    __shared__ unsigned As[16 * 136];   // [k][m], stride 136 (bank-clean frags)
    __shared__ unsigned Bs[16 * 136];   // [k][n]

    const int tid = threadIdx.x;
    const int lane = tid & 31;
    const int w = tid >> 5;
    const int g = lane >> 2;       // group id (row within frag)
    const int t4 = lane & 3;       // thread-in-group (k within frag)
    const int wm = (w >> 2) * 64;
    const int wn = (w & 3) * 32;
    const int m0 = blockIdx.y << 7;
    const int n0 = blockIdx.x << 7;

    const int lm = tid & 127;            // row this thread loads
    const int lk = (tid >> 7) << 2;      // 0 or 4

    const float* Xp = X + (size_t)(m0 + lm) * E_DIM + lk;
    const float* Wp = W + (size_t)(n0 + lm) * E_DIM + lk;

    float c[4][4][4];
#pragma unroll
    for (int i = 0; i < 4; i++)
#pragma unroll
        for (int j = 0; j < 4; j++)
#pragma unroll
            for (int r = 0; r < 4; r++) c[i][j][r] = 0.f;

    for (int k0 = 0; k0 < E_DIM; k0 += 16) {
        float4 xa = *(const float4*)(Xp + k0);
        float4 xb = *(const float4*)(Xp + k0 + 8);
        float4 wa = *(const float4*)(Wp + k0);
        float4 wb = *(const float4*)(Wp + k0 + 8);
        __syncthreads();
        As[(lk + 0) * 136 + lm] = cvt_tf32(xa.x);
        As[(lk + 1) * 136 + lm] = cvt_tf32(xa.y);
        As[(lk + 2) * 136 + lm] = cvt_tf32(xa.z);
        As[(lk + 3) * 136 + lm] = cvt_tf32(xa.w);
        As[(lk + 8) * 136 + lm] = cvt_tf32(xb.x);
        As[(lk + 9) * 136 + lm] = cvt_tf32(xb.y);
        As[(lk + 10) * 136 + lm] = cvt_tf32(xb.z);
        As[(lk + 11) * 136 + lm] = cvt_tf32(xb.w);
        Bs[(lk + 0) * 136 + lm] = cvt_tf32(wa.x);
        Bs[(lk + 1) * 136 + lm] = cvt_tf32(wa.y);
        Bs[(lk + 2) * 136 + lm] = cvt_tf32(wa.z);
        Bs[(lk + 3) * 136 + lm] = cvt_tf32(wa.w);
        Bs[(lk + 8) * 136 + lm] = cvt_tf32(wb.x);
        Bs[(lk + 9) * 136 + lm] = cvt_tf32(wb.y);
        Bs[(lk + 10) * 136 + lm] = cvt_tf32(wb.z);
        Bs[(lk + 11) * 136 + lm] = cvt_tf32(wb.w);
        __syncthreads();

#pragma unroll
        for (int ks = 0; ks < 16; ks += 8) {
            unsigned a[4][4];
#pragma unroll
            for (int i = 0; i < 4; i++) {
                const unsigned* ab = As + (ks + t4) * 136 + wm + i * 16 + g;
                a[i][0] = ab[0];
                a[i][1] = ab[8];
                a[i][2] = ab[4 * 136];
                a[i][3] = ab[4 * 136 + 8];
            }
            unsigned b[4][2];
#pragma unroll
            for (int j = 0; j < 4; j++) {
                const unsigned* bb = Bs + (ks + t4) * 136 + wn + j * 8 + g;
                b[j][0] = bb[0];
                b[j][1] = bb[4 * 136];
            }
#pragma unroll
            for (int i = 0; i < 4; i++)
#pragma unroll
                for (int j = 0; j < 4; j++)
                    mma_m16n8k8(c[i][j], a[i], b[j][0], b[j][1]);
        }
    }

#pragma unroll
    for (int j = 0; j < 4; j++) {
        const int ncol = n0 + wn + j * 8 + 2 * t4;
        const float bv0 = bias[ncol];
        const float bv1 = bias[ncol + 1];
#pragma unroll
        for (int i = 0; i < 4; i++) {
            const int mrow = m0 + wm + i * 16 + g;
            store_out(Y, mrow, ncol, (c[i][j][0] + bv0) * scale,
                      (c[i][j][1] + bv1) * scale, mode);
            store_out(Y, mrow + 8, ncol, (c[i][j][2] + bv0) * scale,
                      (c[i][j][3] + bv1) * scale, mode);
        }
    }
}

// ---------------------------------------------------------------------------
// Flash attention (tf32 tensor cores). Block = (b,h) x 128 queries.
// 8 warps; warp w owns rows [16w, 16w+16) x all 64 keys of the tile.
// ---------------------------------------------------------------------------
#define QS_STR 68
#define KS_STR 68
#define PS_STR 68
#define VS_STR 72
#define SM_Q (128 * QS_STR)
#define SM_K (64 * KS_STR)
#define SM_P (128 * PS_STR)
#define SM_V (64 * VS_STR)
#define FLASH_SMEM ((SM_Q + SM_K + SM_P + SM_V) * 4)

__global__ __launch_bounds__(256) void flash_tc(
    const float* __restrict__ Q, const float* __restrict__ K,
    const float* __restrict__ V, float* __restrict__ ctx)
{
    extern __shared__ unsigned sm[];
    unsigned* Qs = sm;             // [128][68]
    unsigned* Ks = Qs + SM_Q;      // [64][68]
    unsigned* Ps = Ks + SM_K;      // [128][68]
    unsigned* Vs = Ps + SM_P;      // [64][72]

    const int tid = threadIdx.x;
    const int lane = tid & 31;
    const int w = tid >> 5;
    const int g = lane >> 2;
    const int t4 = lane & 3;
    const int wrow = w << 4;
    const int bh = blockIdx.y;
    const int q0 = blockIdx.x << 7;
    const size_t base = (size_t)bh * T_DIM * D_DIM;

    // Load Q tile (128x64) -> Qs (tf32)
#pragma unroll
    for (int i = 0; i < 8; i++) {
        const int ch = tid + i * 256;
        const int r = ch >> 4;
        const int cc = (ch & 15) << 2;
        float4 v = *(const float4*)(Q + base + (size_t)(q0 + r) * D_DIM + cc);
        unsigned* d = Qs + r * QS_STR + cc;
        d[0] = cvt_tf32(v.x); d[1] = cvt_tf32(v.y);
        d[2] = cvt_tf32(v.z); d[3] = cvt_tf32(v.w);
    }

    float o[8][4];
#pragma unroll
    for (int j = 0; j < 8; j++)
#pragma unroll
        for (int r = 0; r < 4; r++) o[j][r] = 0.f;
    float mr0 = -3.0e38f, mr1 = -3.0e38f, l0 = 0.f, l1 = 0.f;

    for (int kt = 0; kt < T_DIM / 64; kt++) {
        const int j0 = kt << 6;
        __syncthreads();   // prior-iter Vs/Ps reads done; Qs visible (1st iter)
#pragma unroll
        for (int i = 0; i < 4; i++) {
            const int ch = tid + i * 256;
            const int r = ch >> 4;
            const int cc = (ch & 15) << 2;
            float4 kv = *(const float4*)(K + base + (size_t)(j0 + r) * D_DIM + cc);
            unsigned* dk = Ks + r * KS_STR + cc;
            dk[0] = cvt_tf32(kv.x); dk[1] = cvt_tf32(kv.y);
            dk[2] = cvt_tf32(kv.z); dk[3] = cvt_tf32(kv.w);
            float4 vv = *(const float4*)(V + base + (size_t)(j0 + r) * D_DIM + cc);
            unsigned* dv = Vs + r * VS_STR + cc;
            dv[0] = cvt_tf32(vv.x); dv[1] = cvt_tf32(vv.y);
            dv[2] = cvt_tf32(vv.z); dv[3] = cvt_tf32(vv.w);
        }
        __syncthreads();

        // S = Q K^T (Q pre-scaled)
        float s[8][4];
#pragma unroll
        for (int j = 0; j < 8; j++)
#pragma unroll
            for (int r = 0; r < 4; r++) s[j][r] = 0.f;

#pragma unroll
        for (int ks = 0; ks < 64; ks += 8) {
            unsigned a[4];
            const unsigned* ab = Qs + (wrow + g) * QS_STR + ks + t4;
            a[0] = ab[0];
            a[1] = ab[8 * QS_STR];
            a[2] = ab[4];
            a[3] = ab[8 * QS_STR + 4];
#pragma unroll
            for (int j = 0; j < 8; j++) {
                const unsigned* bb = Ks + (j * 8 + g) * KS_STR + ks + t4;
                mma_m16n8k8(s[j], a, bb[0], bb[4]);
            }
        }

        // Online softmax (rows wrow+g and wrow+g+8; quad lanes share a row)
        float mx0 = fmaxf(s[0][0], s[0][1]);
        float mx1 = fmaxf(s[0][2], s[0][3]);
#pragma unroll
        for (int j = 1; j < 8; j++) {
            mx0 = fmaxf(mx0, fmaxf(s[j][0], s[j][1]));
            mx1 = fmaxf(mx1, fmaxf(s[j][2], s[j][3]));
        }
        mx0 = fmaxf(mx0, __shfl_xor_sync(0xffffffffu, mx0, 1));
        mx0 = fmaxf(mx0, __shfl_xor_sync(0xffffffffu, mx0, 2));
        mx1 = fmaxf(mx1, __shfl_xor_sync(0xffffffffu, mx1, 1));
        mx1 = fmaxf(mx1, __shfl_xor_sync(0xffffffffu, mx1, 2));

        const float nm0 = fmaxf(mr0, mx0);
        const float nm1 = fmaxf(mr1, mx1);
        const float al0 = fexp(mr0 - nm0);
        const float al1 = fexp(mr1 - nm1);
        mr0 = nm0; mr1 = nm1;

        float rs0 = 0.f, rs1 = 0.f;
        unsigned* p0 = Ps + (wrow + g) * PS_STR + 2 * t4;
        unsigned* p1 = Ps + (wrow + g + 8) * PS_STR + 2 * t4;
#pragma unroll
        for (int j = 0; j < 8; j++) {
            const float e00 = fexp(s[j][0] - nm0);
            const float e01 = fexp(s[j][1] - nm0);
            const float e10 = fexp(s[j][2] - nm1);
            const float e11 = fexp(s[j][3] - nm1);
            rs0 += e00 + e01;
            rs1 += e10 + e11;
            *(uint2*)(p0 + j * 8) = make_uint2(cvt_tf32(e00), cvt_tf32(e01));
            *(uint2*)(p1 + j * 8) = make_uint2(cvt_tf32(e10), cvt_tf32(e11));
            o[j][0] *= al0; o[j][1] *= al0;
            o[j][2] *= al1; o[j][3] *= al1;
        }
        rs0 += __shfl_xor_sync(0xffffffffu, rs0, 1);
        rs0 += __shfl_xor_sync(0xffffffffu, rs0, 2);
        rs1 += __shfl_xor_sync(0xffffffffu, rs1, 1);
        rs1 += __shfl_xor_sync(0xffffffffu, rs1, 2);
        l0 = l0 * al0 + rs0;
        l1 = l1 * al1 + rs1;

        __syncwarp();   // Ps rows are warp-private: warp-level fence suffices

        // O += P @ V
#pragma unroll
        for (int ks = 0; ks < 64; ks += 8) {
            unsigned a[4];
            const unsigned* ab = Ps + (wrow + g) * PS_STR + ks + t4;
            a[0] = ab[0];
            a[1] = ab[8 * PS_STR];
            a[2] = ab[4];
            a[3] = ab[8 * PS_STR + 4];
#pragma unroll
            for (int j = 0; j < 8; j++) {
                const unsigned* bb = Vs + (ks + t4) * VS_STR + j * 8 + g;
                mma_m16n8k8(o[j], a, bb[0], bb[4 * VS_STR]);
            }
        }
    }

    // Epilogue: normalize, write ctx [T,B,E]
    const int b = bh >> 4;
    const int h = bh & 15;
    const float inv0 = 1.f / l0;
    const float inv1 = 1.f / l1;
    const int t0 = q0 + wrow + g;
    const int t1 = t0 + 8;
#pragma unroll
    for (int j = 0; j < 8; j++) {
        const int e = h * D_DIM + j * 8 + 2 * t4;
        *(float2*)(ctx + ((size_t)t0 * B_DIM + b) * E_DIM + e) =
            make_float2(o[j][0] * inv0, o[j][1] * inv0);
        *(float2*)(ctx + ((size_t)t1 * B_DIM + b) * E_DIM + e) =
            make_float2(o[j][2] * inv1, o[j][3] * inv1);
    }
}

// ---------------------------------------------------------------------------
extern "C" void kernel_launch(void* const* d_in, const int* in_sizes, int n_in,
                              void* d_out, int out_size)
{
    const float* x  = (const float*)d_in[0];
    const float* wq = (const float*)d_in[1];
    const float* bq = (const float*)d_in[2];
    const float* wk = (const float*)d_in[3];
    const float* bk = (const float*)d_in[4];
    const float* wv = (const float*)d_in[5];
    const float* bv = (const float*)d_in[6];
    const float* wo = (const float*)d_in[7];
    const float* bo = (const float*)d_in[8];
    float* out = (float*)d_out;

    float *q, *k, *v, *ctx;
    cudaGetSymbolAddress((void**)&q, g_q);
    cudaGetSymbolAddress((void**)&k, g_k);
    cudaGetSymbolAddress((void**)&v, g_v);
    cudaGetSymbolAddress((void**)&ctx, g_ctx);

    const dim3 gg(E_DIM / 128, M_DIM / 128);   // (8, 32)
    const float scaling = 0.125f;              // D^-0.5

    gemm_tc<<<gg, 256>>>(x, wq, bq, scaling, q, 0);
    gemm_tc<<<gg, 256>>>(x, wk, bk, 1.0f,    k, 0);
    gemm_tc<<<gg, 256>>>(x, wv, bv, 1.0f,    v, 0);

    cudaFuncSetAttribute(flash_tc, cudaFuncAttributeMaxDynamicSharedMemorySize,
                         FLASH_SMEM);
    flash_tc<<<dim3(T_DIM / 128, B_DIM * H_DIM), 256, FLASH_SMEM>>>(q, k, v, ctx);

    gemm_tc<<<gg, 256>>>(ctx, wo, bo, 1.0f, out, 1);
}